// round 3
// baseline (speedup 1.0000x reference)
#include <cuda_runtime.h>
#include <cuda_bf16.h>
#include <math.h>

// Scratch (device globals — no allocation allowed)
__device__ float g_h[8 * 2048 * 128];   // h = text @ W
__device__ float g_e1[8 * 2048];
__device__ float g_e2[8 * 2048];
__device__ float g_m2[8];               // per-batch max of e2

#define ALPHA_LR 0.2f

// ---------------------------------------------------------------------------
// f32x2 helpers (Blackwell packed fp32 FMA — only reachable via PTX)
// ---------------------------------------------------------------------------
__device__ __forceinline__ unsigned long long pack_dup(float v) {
    unsigned long long r;
    asm("mov.b64 %0, {%1, %1};" : "=l"(r) : "f"(v));
    return r;
}
__device__ __forceinline__ void fma2(unsigned long long& acc, unsigned long long v,
                                     unsigned long long w) {
    asm("fma.rn.f32x2 %0, %1, %2, %0;" : "+l"(acc) : "l"(v), "l"(w));
}
__device__ __forceinline__ void unpack2(unsigned long long p, float& lo, float& hi) {
    asm("mov.b64 {%0, %1}, %2;" : "=f"(lo), "=f"(hi) : "l"(p));
}

// ---------------------------------------------------------------------------
// Kernel 1: h = text @ W    (16384 x 128) = (16384 x 128) @ (128 x 128)
// Block: 64 rows x 128 cols, 256 threads, K tiled by 32. f32x2 accumulation.
// ---------------------------------------------------------------------------
__global__ __launch_bounds__(256) void gemm_h_kernel(const float* __restrict__ text,
                                                     const float* __restrict__ W) {
    __shared__ float ts[64][33];    // padded: bank(il*33+kk) = (il+kk)%32, conflict-free
    __shared__ float ws[32][128];

    const int tid = threadIdx.x;
    const int il  = tid & 63;       // row within tile
    const int fg  = tid >> 6;       // 0..3, handles cols fg*32 .. fg*32+31
    const size_t row0 = (size_t)blockIdx.x * 64;

    unsigned long long acc[16];
#pragma unroll
    for (int m = 0; m < 16; m++) acc[m] = 0ULL;

    for (int k0 = 0; k0 < 128; k0 += 32) {
        __syncthreads();
        // text tile 64x32 (512 float4s, 2 per thread)
#pragma unroll
        for (int q = 0; q < 2; q++) {
            int idx = tid + q * 256;
            int r   = idx >> 3;
            int kk4 = idx & 7;
            float4 v = *(const float4*)(text + (row0 + r) * 128 + k0 + kk4 * 4);
            ts[r][kk4 * 4 + 0] = v.x; ts[r][kk4 * 4 + 1] = v.y;
            ts[r][kk4 * 4 + 2] = v.z; ts[r][kk4 * 4 + 3] = v.w;
        }
        // W chunk 32x128 (1024 float4s, 4 per thread)
#pragma unroll
        for (int q = 0; q < 4; q++) {
            int idx = tid + q * 256;
            int kr  = idx >> 5;
            int c4  = idx & 31;
            *(float4*)(&ws[kr][c4 * 4]) = *(const float4*)(W + (size_t)(k0 + kr) * 128 + c4 * 4);
        }
        __syncthreads();

#pragma unroll
        for (int kk = 0; kk < 32; kk++) {
            unsigned long long a2 = pack_dup(ts[il][kk]);
            const ulonglong2* wr = (const ulonglong2*)(&ws[kk][fg * 32]);
#pragma unroll
            for (int m = 0; m < 8; m++) {
                ulonglong2 v = wr[m];        // LDS.128, warp-broadcast
                fma2(acc[2 * m],     v.x, a2);
                fma2(acc[2 * m + 1], v.y, a2);
            }
        }
    }

    float* hrow = g_h + (row0 + il) * 128 + fg * 32;
#pragma unroll
    for (int m = 0; m < 8; m++) {
        float4 o;
        unpack2(acc[2 * m],     o.x, o.y);
        unpack2(acc[2 * m + 1], o.z, o.w);
        *(float4*)(hrow + m * 4) = o;
    }
}

// ---------------------------------------------------------------------------
// Kernel 2: e1[row] = h[row,:].a1 ; e2[row] = h[row,:].a2   (warp per row)
// ---------------------------------------------------------------------------
__global__ __launch_bounds__(256) void e_kernel(const float* __restrict__ a) {
    const int warp = threadIdx.x >> 5;
    const int lane = threadIdx.x & 31;
    const size_t row = (size_t)blockIdx.x * 8 + warp;

    float4 hv = *(const float4*)(g_h + row * 128 + lane * 4);
    float4 a1 = *(const float4*)(a + lane * 4);
    float4 a2 = *(const float4*)(a + 128 + lane * 4);

    float s1 = hv.x * a1.x + hv.y * a1.y + hv.z * a1.z + hv.w * a1.w;
    float s2 = hv.x * a2.x + hv.y * a2.y + hv.z * a2.z + hv.w * a2.w;
#pragma unroll
    for (int o = 16; o > 0; o >>= 1) {
        s1 += __shfl_xor_sync(0xFFFFFFFFu, s1, o);
        s2 += __shfl_xor_sync(0xFFFFFFFFu, s2, o);
    }
    if (lane == 0) { g_e1[row] = s1; g_e2[row] = s2; }
}

// ---------------------------------------------------------------------------
// Kernel 3: m2[b] = max_j e2[b,j]
// ---------------------------------------------------------------------------
__global__ __launch_bounds__(256) void max_kernel() {
    __shared__ float red[256];
    const int b = blockIdx.x;
    float m = -INFINITY;
    for (int j = threadIdx.x; j < 2048; j += 256) m = fmaxf(m, g_e2[b * 2048 + j]);
    red[threadIdx.x] = m;
    __syncthreads();
    for (int s = 128; s > 0; s >>= 1) {
        if (threadIdx.x < s) red[threadIdx.x] = fmaxf(red[threadIdx.x], red[threadIdx.x + s]);
        __syncthreads();
    }
    if (threadIdx.x == 0) g_m2[b] = red[0];
}

// ---------------------------------------------------------------------------
// Kernel 4: main attention.
//   w_ij = exp(LR(e1_i + e2_j) - m_i),  m_i = LR(e1_i + max_j e2_j)  (LR monotone)
//   out[b,i,:] = elu( (sum_j w_ij h[j,:]) / (sum_j w_ij) + 0.2*h[i,:] )
// Block: 64 i-rows x all 128 f, 256 threads; loop j in tiles of 64 via smem.
// f32x2 accumulators, smem reads are warp-broadcast (no conflicts).
// ---------------------------------------------------------------------------
__global__ __launch_bounds__(256) void attn_kernel(float* __restrict__ out) {
    __shared__ float hs[64][128];
    __shared__ float es[64];

    const int tid = threadIdx.x;
    const int il  = tid & 63;
    const int fg  = tid >> 6;
    const int b   = blockIdx.y;
    const size_t base = (size_t)b * 2048;
    const size_t i    = (size_t)blockIdx.x * 64 + il;
    const float* hb   = g_h + base * 128;

    const float e1i = g_e1[base + i];
    const float ms  = e1i + g_m2[b];
    const float mi  = ms > 0.f ? ms : ALPHA_LR * ms;

    unsigned long long acc[16];
#pragma unroll
    for (int m = 0; m < 16; m++) acc[m] = 0ULL;
    float wsum = 0.f;

    for (int jt = 0; jt < 2048; jt += 64) {
        __syncthreads();
        {   // cooperative tile load: 64x128 floats = 2048 float4s, 8 per thread
            const float4* src = (const float4*)(hb + (size_t)jt * 128);
            float4* dst = (float4*)(&hs[0][0]);
#pragma unroll
            for (int q = 0; q < 8; q++) dst[tid + 256 * q] = src[tid + 256 * q];
            if (tid < 64) es[tid] = g_e2[base + jt + tid];
        }
        __syncthreads();

#pragma unroll 4
        for (int j = 0; j < 64; j++) {
            float s  = e1i + es[j];
            float lr = fmaxf(s, 0.f) + ALPHA_LR * fminf(s, 0.f);
            float w  = __expf(lr - mi);            // arg <= 0, underflow -> 0 ok
            wsum += w;
            unsigned long long w2 = pack_dup(w);
            const ulonglong2* hr = (const ulonglong2*)(&hs[j][fg * 32]);
#pragma unroll
            for (int m = 0; m < 8; m++) {
                ulonglong2 v = hr[m];              // LDS.128, warp-broadcast
                fma2(acc[2 * m],     v.x, w2);
                fma2(acc[2 * m + 1], v.y, w2);
            }
        }
    }

    const float rs = 1.0f / wsum;
    const float* hrow = hb + i * 128 + fg * 32;
    float* orow = out + (base + i) * 128 + fg * 32;
#pragma unroll
    for (int m = 0; m < 8; m++) {
        float p0, p1, p2, p3;
        unpack2(acc[2 * m],     p0, p1);
        unpack2(acc[2 * m + 1], p2, p3);
        float4 hv = *(const float4*)(hrow + m * 4);
        float4 o;
        float x;
        x = fmaf(p0, rs, ALPHA_LR * hv.x); o.x = x > 0.f ? x : expm1f(x);
        x = fmaf(p1, rs, ALPHA_LR * hv.y); o.y = x > 0.f ? x : expm1f(x);
        x = fmaf(p2, rs, ALPHA_LR * hv.z); o.z = x > 0.f ? x : expm1f(x);
        x = fmaf(p3, rs, ALPHA_LR * hv.w); o.w = x > 0.f ? x : expm1f(x);
        *(float4*)(orow + m * 4) = o;
    }
}

// ---------------------------------------------------------------------------
// Launch: text, adj(UNUSED by reference!), W, a
// ---------------------------------------------------------------------------
extern "C" void kernel_launch(void* const* d_in, const int* in_sizes, int n_in,
                              void* d_out, int out_size) {
    const float* text = (const float*)d_in[0];
    // d_in[1] = adj — the reference computation never uses it; skip 134 MB of reads.
    const float* W = (const float*)d_in[2];
    const float* a = (const float*)d_in[3];
    float* out = (float*)d_out;

    gemm_h_kernel<<<256, 256>>>(text, W);   // 16384/64 row-tiles
    e_kernel<<<2048, 256>>>(a);             // 8 rows (warps) per block
    max_kernel<<<8, 256>>>();
    dim3 grid(32, 8);                        // 2048/64 i-tiles x 8 batches
    attn_kernel<<<grid, 256>>>(out);
}